// round 1
// baseline (speedup 1.0000x reference)
#include <cuda_runtime.h>

// Problem constants
#define B_  128
#define H_  16
#define L_  64
#define E_  128
#define C_  2048          // H*E
#define M_  8192          // B*L

// Intermediate V in [B*L, H*E] layout (64 MB) — static device scratch (no allocs allowed)
__device__ float g_vbuf[(size_t)M_ * C_];

// ---------------------------------------------------------------------------
// Attention kernel: one block per (b,h). q,k,v tiles (64x128) in smem with
// row stride 132 (multiple of 4 for float4 alignment; 132 mod 32 = 4 so four
// consecutive rows hit distinct bank groups -> conflict-free float4 reads).
// ---------------------------------------------------------------------------
#define SQS 132           // padded row stride for q/k/v tiles
#define SAS 65            // padded row stride for scores tile

__global__ __launch_bounds__(256, 1)
void attn_kernel(const float* __restrict__ Q, const float* __restrict__ K,
                 const float* __restrict__ V)
{
    extern __shared__ float sm[];
    float* sq = sm;                    // 64*132
    float* sk = sq + L_ * SQS;         // 64*132
    float* sv = sk + L_ * SQS;         // 64*132
    float* sA = sv + L_ * SQS;         // 64*65

    const int bh = blockIdx.x;
    const int b  = bh >> 4;            // H_ = 16
    const int h  = bh & 15;
    const float* qb = Q + (size_t)bh * (L_ * E_);
    const float* kb = K + (size_t)bh * (L_ * E_);
    const float* vb = V + (size_t)bh * (L_ * E_);

    const int t = threadIdx.x;

    // Load q,k,v tiles (64x128 floats each = 2048 float4) into padded smem
    for (int idx = t; idx < (L_ * E_) / 4; idx += 256) {
        int row = idx >> 5;            // E_/4 = 32 float4 per row
        int c4  = (idx & 31) << 2;
        float4 q4 = __ldg((const float4*)(qb + row * E_ + c4));
        float4 k4 = __ldg((const float4*)(kb + row * E_ + c4));
        float4 v4 = __ldg((const float4*)(vb + row * E_ + c4));
        *(float4*)(sq + row * SQS + c4) = q4;
        *(float4*)(sk + row * SQS + c4) = k4;
        *(float4*)(sv + row * SQS + c4) = v4;
    }
    __syncthreads();

    // Scores: thread t handles l = t/4, s in { (t&3) + 4j : j=0..15 }
    const int l = t >> 2;
    const int c = t & 3;
    float sc[16];
#pragma unroll
    for (int j = 0; j < 16; j++) sc[j] = 0.f;

    for (int e = 0; e < E_; e += 4) {
        const float4 qv = *(const float4*)(sq + l * SQS + e);
#pragma unroll
        for (int j = 0; j < 16; j++) {
            const float4 kv = *(const float4*)(sk + (c + 4 * j) * SQS + e);
            sc[j] += qv.x * kv.x + qv.y * kv.y + qv.z * kv.z + qv.w * kv.w;
        }
    }
#pragma unroll
    for (int j = 0; j < 16; j++) sA[l * SAS + c + 4 * j] = sc[j];
    __syncthreads();

    // Softmax over s (row length 64), scale = 0.1
    if (t < 64) {
        float* row = sA + t * SAS;
        float mx = -1e30f;
#pragma unroll 8
        for (int s = 0; s < 64; s++) mx = fmaxf(mx, row[s]);
        float sum = 0.f;
#pragma unroll 8
        for (int s = 0; s < 64; s++) {
            float ex = __expf(0.1f * (row[s] - mx));
            row[s] = ex;
            sum += ex;
        }
        float inv = 1.0f / sum;
#pragma unroll 8
        for (int s = 0; s < 64; s++) row[s] *= inv;
    }
    __syncthreads();

    // A @ v: thread t handles l = t/4, d in { (t&3)*4 + 16j + i : j=0..7, i=0..3 }
    float acc[32];
#pragma unroll
    for (int i = 0; i < 32; i++) acc[i] = 0.f;

    for (int s = 0; s < 64; s++) {
        const float a = sA[l * SAS + s];
#pragma unroll
        for (int j = 0; j < 8; j++) {
            const float4 vv = *(const float4*)(sv + s * SQS + (c << 2) + (j << 4));
            acc[4 * j + 0] += a * vv.x;
            acc[4 * j + 1] += a * vv.y;
            acc[4 * j + 2] += a * vv.z;
            acc[4 * j + 3] += a * vv.w;
        }
    }

    // Write V to [B*L, H*E]: row = b*64 + l, col = h*128 + d
    float* outp = g_vbuf + ((size_t)(b * L_ + l) * H_ + h) * E_;
#pragma unroll
    for (int j = 0; j < 8; j++) {
        *(float4*)(outp + (c << 2) + (j << 4)) =
            make_float4(acc[4 * j + 0], acc[4 * j + 1], acc[4 * j + 2], acc[4 * j + 3]);
    }
}

// ---------------------------------------------------------------------------
// Projection GEMM: out[M_, C_] = g_vbuf[M_, C_] @ W[C_, C_]^T + bias
// Classic 128x128x8 SGEMM, 256 threads, 8x8 register microtile.
// ---------------------------------------------------------------------------
#define BM 128
#define BN 128
#define BK 8

__global__ __launch_bounds__(256, 2)
void gemm_kernel(const float* __restrict__ W, const float* __restrict__ bias,
                 float* __restrict__ out)
{
    __shared__ float As[BK][BM];   // As[k][m]
    __shared__ float Bs[BK][BN];   // Bs[k][n]  (n indexes rows of W)

    const int t  = threadIdx.x;
    const int m0 = blockIdx.y * BM;
    const int n0 = blockIdx.x * BN;

    const int lrow = t >> 1;           // 0..127
    const int lc4  = (t & 1) << 2;     // 0 or 4

    const float* Ap = g_vbuf + (size_t)(m0 + lrow) * C_ + lc4;
    const float* Wp = W      + (size_t)(n0 + lrow) * C_ + lc4;

    const int tm = (t >> 4) << 3;      // 0..120
    const int tn = (t & 15) << 3;      // 0..120

    float acc[8][8];
#pragma unroll
    for (int i = 0; i < 8; i++)
#pragma unroll
        for (int j = 0; j < 8; j++) acc[i][j] = 0.f;

    for (int k0 = 0; k0 < C_; k0 += BK) {
        const float4 av = __ldg((const float4*)(Ap + k0));
        const float4 wv = __ldg((const float4*)(Wp + k0));
        __syncthreads();   // previous tile fully consumed
        As[lc4 + 0][lrow] = av.x;
        As[lc4 + 1][lrow] = av.y;
        As[lc4 + 2][lrow] = av.z;
        As[lc4 + 3][lrow] = av.w;
        Bs[lc4 + 0][lrow] = wv.x;
        Bs[lc4 + 1][lrow] = wv.y;
        Bs[lc4 + 2][lrow] = wv.z;
        Bs[lc4 + 3][lrow] = wv.w;
        __syncthreads();

#pragma unroll
        for (int kk = 0; kk < BK; kk++) {
            float a[8], bb[8];
            *(float4*)(a)      = *(const float4*)&As[kk][tm];
            *(float4*)(a + 4)  = *(const float4*)&As[kk][tm + 4];
            *(float4*)(bb)     = *(const float4*)&Bs[kk][tn];
            *(float4*)(bb + 4) = *(const float4*)&Bs[kk][tn + 4];
#pragma unroll
            for (int i = 0; i < 8; i++)
#pragma unroll
                for (int j = 0; j < 8; j++)
                    acc[i][j] += a[i] * bb[j];
        }
    }

    // Epilogue: add bias, write out
    float bv[8];
    *(float4*)(bv)     = __ldg((const float4*)(bias + n0 + tn));
    *(float4*)(bv + 4) = __ldg((const float4*)(bias + n0 + tn + 4));

#pragma unroll
    for (int i = 0; i < 8; i++) {
        float* op = out + (size_t)(m0 + tm + i) * C_ + n0 + tn;
        *(float4*)(op)     = make_float4(acc[i][0] + bv[0], acc[i][1] + bv[1],
                                         acc[i][2] + bv[2], acc[i][3] + bv[3]);
        *(float4*)(op + 4) = make_float4(acc[i][4] + bv[4], acc[i][5] + bv[5],
                                         acc[i][6] + bv[6], acc[i][7] + bv[7]);
    }
}

// ---------------------------------------------------------------------------
extern "C" void kernel_launch(void* const* d_in, const int* in_sizes, int n_in,
                              void* d_out, int out_size)
{
    const float* Q    = (const float*)d_in[0];
    const float* K    = (const float*)d_in[1];
    const float* V    = (const float*)d_in[2];
    const float* W    = (const float*)d_in[3];
    const float* bias = (const float*)d_in[4];
    float* out = (float*)d_out;

    const int smem_bytes = (3 * L_ * SQS + L_ * SAS) * (int)sizeof(float);  // ~115 KB
    cudaFuncSetAttribute(attn_kernel, cudaFuncAttributeMaxDynamicSharedMemorySize, smem_bytes);

    attn_kernel<<<B_ * H_, 256, smem_bytes>>>(Q, K, V);

    dim3 grid(C_ / BN, M_ / BM);   // (16, 64)
    gemm_kernel<<<grid, 256>>>(W, bias, out);
}

// round 3
// speedup vs baseline: 1.9098x; 1.9098x over previous
#include <cuda_runtime.h>
#include <cuda_bf16.h>
#include <cstdint>

// Problem constants
#define B_  128
#define H_  16
#define L_  64
#define E_  128
#define C_  2048          // H*E
#define M_  8192          // B*L

// bf16 split planes (static device scratch — no allocs allowed)
__device__ __align__(16) __nv_bfloat16 g_abf_hi[(size_t)M_ * C_];
__device__ __align__(16) __nv_bfloat16 g_abf_lo[(size_t)M_ * C_];
__device__ __align__(16) __nv_bfloat16 g_wbf_hi[(size_t)C_ * C_];
__device__ __align__(16) __nv_bfloat16 g_wbf_lo[(size_t)C_ * C_];

// ---------------------------------------------------------------------------
// Helpers
// ---------------------------------------------------------------------------
__device__ __forceinline__ uint32_t smem_u32(const void* p) {
    uint32_t a;
    asm("{ .reg .u64 t; cvta.to.shared.u64 t, %1; cvt.u32.u64 %0, t; }" : "=r"(a) : "l"(p));
    return a;
}
__device__ __forceinline__ void cpa16(uint32_t dst, const void* src) {
    asm volatile("cp.async.cg.shared.global [%0], [%1], 16;" :: "r"(dst), "l"(src) : "memory");
}
__device__ __forceinline__ void cpa_commit() { asm volatile("cp.async.commit_group;" ::: "memory"); }
__device__ __forceinline__ void cpa_wait1()  { asm volatile("cp.async.wait_group 1;" ::: "memory"); }
__device__ __forceinline__ void cpa_wait0()  { asm volatile("cp.async.wait_group 0;" ::: "memory"); }

__device__ __forceinline__ void ldsm4(uint32_t* r, uint32_t addr) {
    asm volatile("ldmatrix.sync.aligned.m8n8.x4.shared.b16 {%0,%1,%2,%3}, [%4];"
                 : "=r"(r[0]), "=r"(r[1]), "=r"(r[2]), "=r"(r[3]) : "r"(addr));
}
__device__ __forceinline__ void mma_bf16(float* d, const uint32_t* a, const uint32_t* b) {
    asm volatile(
        "mma.sync.aligned.m16n8k16.row.col.f32.bf16.bf16.f32 "
        "{%0,%1,%2,%3}, {%4,%5,%6,%7}, {%8,%9}, {%0,%1,%2,%3};"
        : "+f"(d[0]), "+f"(d[1]), "+f"(d[2]), "+f"(d[3])
        : "r"(a[0]), "r"(a[1]), "r"(a[2]), "r"(a[3]), "r"(b[0]), "r"(b[1]));
}

__device__ __forceinline__ uint32_t pack_bf2(float a, float b) {
    __nv_bfloat162 t = __floats2bfloat162_rn(a, b);
    return *reinterpret_cast<uint32_t*>(&t);
}
__device__ __forceinline__ float bfr(float x) {
    return __bfloat162float(__float2bfloat16(x));
}

// ---------------------------------------------------------------------------
// W conversion: fp32 -> bf16 hi/lo planes (K-major, same layout as W)
// ---------------------------------------------------------------------------
__global__ __launch_bounds__(256)
void conv_w_kernel(const float* __restrict__ W)
{
    size_t i = (size_t)blockIdx.x * 256 + threadIdx.x;
    float4 w = __ldg(((const float4*)W) + i);
    float hx = bfr(w.x), hy = bfr(w.y), hz = bfr(w.z), hw = bfr(w.w);
    ((uint2*)g_wbf_hi)[i] = make_uint2(pack_bf2(hx, hy), pack_bf2(hz, hw));
    ((uint2*)g_wbf_lo)[i] = make_uint2(pack_bf2(w.x - hx, w.y - hy), pack_bf2(w.z - hz, w.w - hw));
}

// ---------------------------------------------------------------------------
// Attention kernel: epilogue writes bf16 hi/lo planes of V
// ---------------------------------------------------------------------------
#define SQS 132
#define SAS 65

__global__ __launch_bounds__(256, 1)
void attn_kernel(const float* __restrict__ Q, const float* __restrict__ K,
                 const float* __restrict__ V)
{
    extern __shared__ float sm[];
    float* sq = sm;
    float* sk = sq + L_ * SQS;
    float* sv = sk + L_ * SQS;
    float* sA = sv + L_ * SQS;

    const int bh = blockIdx.x;
    const int b  = bh >> 4;
    const int h  = bh & 15;
    const float* qb = Q + (size_t)bh * (L_ * E_);
    const float* kb = K + (size_t)bh * (L_ * E_);
    const float* vb = V + (size_t)bh * (L_ * E_);

    const int t = threadIdx.x;

    for (int idx = t; idx < (L_ * E_) / 4; idx += 256) {
        int row = idx >> 5;
        int c4  = (idx & 31) << 2;
        float4 q4 = __ldg((const float4*)(qb + row * E_ + c4));
        float4 k4 = __ldg((const float4*)(kb + row * E_ + c4));
        float4 v4 = __ldg((const float4*)(vb + row * E_ + c4));
        *(float4*)(sq + row * SQS + c4) = q4;
        *(float4*)(sk + row * SQS + c4) = k4;
        *(float4*)(sv + row * SQS + c4) = v4;
    }
    __syncthreads();

    const int l = t >> 2;
    const int c = t & 3;
    float sc[16];
#pragma unroll
    for (int j = 0; j < 16; j++) sc[j] = 0.f;

    for (int e = 0; e < E_; e += 4) {
        const float4 qv = *(const float4*)(sq + l * SQS + e);
#pragma unroll
        for (int j = 0; j < 16; j++) {
            const float4 kv = *(const float4*)(sk + (c + 4 * j) * SQS + e);
            sc[j] += qv.x * kv.x + qv.y * kv.y + qv.z * kv.z + qv.w * kv.w;
        }
    }
#pragma unroll
    for (int j = 0; j < 16; j++) sA[l * SAS + c + 4 * j] = sc[j];
    __syncthreads();

    if (t < 64) {
        float* row = sA + t * SAS;
        float mx = -1e30f;
#pragma unroll 8
        for (int s = 0; s < 64; s++) mx = fmaxf(mx, row[s]);
        float sum = 0.f;
#pragma unroll 8
        for (int s = 0; s < 64; s++) {
            float ex = __expf(0.1f * (row[s] - mx));
            row[s] = ex;
            sum += ex;
        }
        float inv = 1.0f / sum;
#pragma unroll 8
        for (int s = 0; s < 64; s++) row[s] *= inv;
    }
    __syncthreads();

    float acc[32];
#pragma unroll
    for (int i = 0; i < 32; i++) acc[i] = 0.f;

    for (int s = 0; s < 64; s++) {
        const float a = sA[l * SAS + s];
#pragma unroll
        for (int j = 0; j < 8; j++) {
            const float4 vv = *(const float4*)(sv + s * SQS + (c << 2) + (j << 4));
            acc[4 * j + 0] += a * vv.x;
            acc[4 * j + 1] += a * vv.y;
            acc[4 * j + 2] += a * vv.z;
            acc[4 * j + 3] += a * vv.w;
        }
    }

    const size_t base = (size_t)(b * L_ + l) * C_ + h * E_;
#pragma unroll
    for (int j = 0; j < 8; j++) {
        const int off = (c << 2) + (j << 4);
        float x0 = acc[4 * j + 0], x1 = acc[4 * j + 1];
        float x2 = acc[4 * j + 2], x3 = acc[4 * j + 3];
        float h0 = bfr(x0), h1 = bfr(x1), h2 = bfr(x2), h3 = bfr(x3);
        *(uint2*)(g_abf_hi + base + off) = make_uint2(pack_bf2(h0, h1), pack_bf2(h2, h3));
        *(uint2*)(g_abf_lo + base + off) =
            make_uint2(pack_bf2(x0 - h0, x1 - h1), pack_bf2(x2 - h2, x3 - h3));
    }
}

// ---------------------------------------------------------------------------
// HMMA split-bf16 GEMM: out[8192,2048] = A @ W^T + bias
// Tile 128x128, 8 warps (32x64 each), BK=32, 2-stage cp.async pipeline.
// smem tile rows padded to 80B (stride 5 in 16B units -> conflict-free ldmatrix)
// ---------------------------------------------------------------------------
#define GBM 128
#define GBN 128
#define GBK 32
#define NKT (C_ / GBK)            // 64 k-steps
#define TROW 80                   // bytes per smem tile row
#define TILE_BYTES (128 * TROW)   // 10240
#define STAGE_BYTES (4 * TILE_BYTES)   // 40960: Ah, Al, Bh, Bl
#define GEMM_SMEM (2 * STAGE_BYTES)    // 81920

__device__ __forceinline__ void load_stage(uint32_t st, int m0, int n0, int k0, int t)
{
    const char* ah = (const char*)(g_abf_hi + (size_t)m0 * C_ + k0);
    const char* al = (const char*)(g_abf_lo + (size_t)m0 * C_ + k0);
    const char* bh = (const char*)(g_wbf_hi + (size_t)n0 * C_ + k0);
    const char* bl = (const char*)(g_wbf_lo + (size_t)n0 * C_ + k0);
#pragma unroll
    for (int j = 0; j < 8; j++) {
        const int tile = j >> 1;                    // 0..3
        const int r = (j * 64 + (t >> 2)) & 127;    // row within tile
        const int c = t & 3;                        // 16B chunk within row
        const char* base = (tile == 0) ? ah : (tile == 1) ? al : (tile == 2) ? bh : bl;
        cpa16(st + tile * TILE_BYTES + r * TROW + c * 16,
              base + (size_t)r * (C_ * 2) + c * 16);
    }
}

__global__ __launch_bounds__(256, 1)
void gemm_hmma(const float* __restrict__ bias, float* __restrict__ out)
{
    extern __shared__ char smem_raw[];
    const uint32_t sb = smem_u32(smem_raw);

    const int t    = threadIdx.x;
    const int wid  = t >> 5;
    const int lane = t & 31;
    const int n0   = blockIdx.x * GBN;
    const int m0   = blockIdx.y * GBM;
    const int wm   = (wid & 3) * 32;      // warp m offset (4 warps on M)
    const int wn   = (wid >> 2) * 64;     // warp n offset (2 warps on N)

    // ldmatrix per-lane offsets (bytes, within tile)
    const uint32_t a_off = (uint32_t)((lane & 15) * TROW + (lane >> 4) * 16);
    const uint32_t b_off = (uint32_t)(((lane & 7) + ((lane >> 4) << 3)) * TROW
                                      + ((lane >> 3) & 1) * 16);

    float acc[2][8][4];
#pragma unroll
    for (int i = 0; i < 2; i++)
#pragma unroll
        for (int j = 0; j < 8; j++)
#pragma unroll
            for (int q = 0; q < 4; q++) acc[i][j][q] = 0.f;

    load_stage(sb, m0, n0, 0, t);
    cpa_commit();

    for (int kt = 0; kt < NKT; kt++) {
        if (kt + 1 < NKT) {
            load_stage(sb + ((kt + 1) & 1) * STAGE_BYTES, m0, n0, (kt + 1) * GBK, t);
            cpa_commit();
            cpa_wait1();
        } else {
            cpa_wait0();
        }
        __syncthreads();

        const uint32_t st = sb + (kt & 1) * STAGE_BYTES;
#pragma unroll
        for (int kk = 0; kk < 2; kk++) {
            const uint32_t kb = kk * 32;    // 16 bf16 = 32 bytes
            uint32_t Ah[2][4], Al[2][4], Bh[4][4], Bl[4][4];
#pragma unroll
            for (int mi = 0; mi < 2; mi++) {
                ldsm4(Ah[mi], st + 0 * TILE_BYTES + a_off + (wm + mi * 16) * TROW + kb);
                ldsm4(Al[mi], st + 1 * TILE_BYTES + a_off + (wm + mi * 16) * TROW + kb);
            }
#pragma unroll
            for (int p = 0; p < 4; p++) {
                ldsm4(Bh[p], st + 2 * TILE_BYTES + b_off + (wn + p * 16) * TROW + kb);
                ldsm4(Bl[p], st + 3 * TILE_BYTES + b_off + (wn + p * 16) * TROW + kb);
            }
#pragma unroll
            for (int mi = 0; mi < 2; mi++)
#pragma unroll
                for (int p = 0; p < 4; p++) {
                    mma_bf16(acc[mi][2 * p],     Ah[mi], Bh[p]);
                    mma_bf16(acc[mi][2 * p + 1], Ah[mi], Bh[p] + 2);
                    mma_bf16(acc[mi][2 * p],     Ah[mi], Bl[p]);
                    mma_bf16(acc[mi][2 * p + 1], Ah[mi], Bl[p] + 2);
                    mma_bf16(acc[mi][2 * p],     Al[mi], Bh[p]);
                    mma_bf16(acc[mi][2 * p + 1], Al[mi], Bh[p] + 2);
                }
        }
        __syncthreads();
    }

    // Epilogue: bias + store. Fragment: c0,c1 at (row=g, col=2q), c2,c3 at row g+8.
    const int g  = lane >> 2;
    const int q2 = (lane & 3) * 2;
    float2 bvs[8];
#pragma unroll
    for (int j = 0; j < 8; j++) {
        const int col = n0 + wn + j * 8 + q2;
        bvs[j] = make_float2(__ldg(bias + col), __ldg(bias + col + 1));
    }
#pragma unroll
    for (int mi = 0; mi < 2; mi++) {
        const int row = m0 + wm + mi * 16 + g;
#pragma unroll
        for (int j = 0; j < 8; j++) {
            const int col = n0 + wn + j * 8 + q2;
            *(float2*)(out + (size_t)row * C_ + col) =
                make_float2(acc[mi][j][0] + bvs[j].x, acc[mi][j][1] + bvs[j].y);
            *(float2*)(out + (size_t)(row + 8) * C_ + col) =
                make_float2(acc[mi][j][2] + bvs[j].x, acc[mi][j][3] + bvs[j].y);
        }
    }
}

// ---------------------------------------------------------------------------
extern "C" void kernel_launch(void* const* d_in, const int* in_sizes, int n_in,
                              void* d_out, int out_size)
{
    const float* Q    = (const float*)d_in[0];
    const float* K    = (const float*)d_in[1];
    const float* V    = (const float*)d_in[2];
    const float* W    = (const float*)d_in[3];
    const float* bias = (const float*)d_in[4];
    float* out = (float*)d_out;

    const int attn_smem = (3 * L_ * SQS + L_ * SAS) * (int)sizeof(float);
    cudaFuncSetAttribute(attn_kernel, cudaFuncAttributeMaxDynamicSharedMemorySize, attn_smem);
    cudaFuncSetAttribute(gemm_hmma, cudaFuncAttributeMaxDynamicSharedMemorySize, GEMM_SMEM);

    conv_w_kernel<<<(C_ * C_ / 4) / 256, 256>>>(W);
    attn_kernel<<<B_ * H_, 256, attn_smem>>>(Q, K, V);
    gemm_hmma<<<dim3(C_ / GBN, M_ / GBM), 256, GEMM_SMEM>>>(bias, out);
}

// round 4
// speedup vs baseline: 3.9329x; 2.0594x over previous
#include <cuda_runtime.h>
#include <cuda_fp16.h>
#include <cstdint>

// Problem constants
#define B_  128
#define H_  16
#define L_  64
#define E_  128
#define C_  2048          // H*E
#define M_  8192          // B*L

// fp16 operand planes (static device scratch — no allocs allowed)
__device__ __align__(16) __half g_a16[(size_t)M_ * C_];
__device__ __align__(16) __half g_w16[(size_t)C_ * C_];

// ---------------------------------------------------------------------------
// Helpers
// ---------------------------------------------------------------------------
__device__ __forceinline__ uint32_t smem_u32(const void* p) {
    uint32_t a;
    asm("{ .reg .u64 t; cvta.to.shared.u64 t, %1; cvt.u32.u64 %0, t; }" : "=r"(a) : "l"(p));
    return a;
}
__device__ __forceinline__ void cpa16(uint32_t dst, const void* src) {
    asm volatile("cp.async.cg.shared.global [%0], [%1], 16;" :: "r"(dst), "l"(src) : "memory");
}
__device__ __forceinline__ void cpa_commit() { asm volatile("cp.async.commit_group;" ::: "memory"); }
__device__ __forceinline__ void cpa_wait3()  { asm volatile("cp.async.wait_group 3;" ::: "memory"); }
__device__ __forceinline__ void cpa_wait2()  { asm volatile("cp.async.wait_group 2;" ::: "memory"); }
__device__ __forceinline__ void cpa_wait1()  { asm volatile("cp.async.wait_group 1;" ::: "memory"); }
__device__ __forceinline__ void cpa_wait0()  { asm volatile("cp.async.wait_group 0;" ::: "memory"); }

__device__ __forceinline__ void ldsm4(uint32_t* r, uint32_t addr) {
    asm volatile("ldmatrix.sync.aligned.m8n8.x4.shared.b16 {%0,%1,%2,%3}, [%4];"
                 : "=r"(r[0]), "=r"(r[1]), "=r"(r[2]), "=r"(r[3]) : "r"(addr));
}
__device__ __forceinline__ void mma_f16(float* d, const uint32_t* a, const uint32_t* b) {
    asm volatile(
        "mma.sync.aligned.m16n8k16.row.col.f32.f16.f16.f32 "
        "{%0,%1,%2,%3}, {%4,%5,%6,%7}, {%8,%9}, {%0,%1,%2,%3};"
        : "+f"(d[0]), "+f"(d[1]), "+f"(d[2]), "+f"(d[3])
        : "r"(a[0]), "r"(a[1]), "r"(a[2]), "r"(a[3]), "r"(b[0]), "r"(b[1]));
}
__device__ __forceinline__ uint32_t pack_h2(float a, float b) {
    __half2 t = __floats2half2_rn(a, b);
    return *reinterpret_cast<uint32_t*>(&t);
}

// ---------------------------------------------------------------------------
// W conversion: fp32 -> fp16
// ---------------------------------------------------------------------------
__global__ __launch_bounds__(256)
void conv_w_kernel(const float* __restrict__ W)
{
    size_t i = (size_t)blockIdx.x * 256 + threadIdx.x;   // over C_*C_/4 float4
    float4 w = __ldg(((const float4*)W) + i);
    ((uint2*)g_w16)[i] = make_uint2(pack_h2(w.x, w.y), pack_h2(w.z, w.w));
}

// ---------------------------------------------------------------------------
// Attention kernel: fp32 core, register softmax, epilogue writes fp16 A.
// smem: sq/sk/sv tiles (64x132 fp32); scores buffer aliases sq after QK^T.
// 99 KB total -> 2 CTAs/SM.
// ---------------------------------------------------------------------------
#define SQS 132
#define SAS 65
#define ATTN_SMEM (3 * L_ * SQS * (int)sizeof(float))   // 101376 B

__global__ __launch_bounds__(256, 2)
void attn_kernel(const float* __restrict__ Q, const float* __restrict__ K,
                 const float* __restrict__ V)
{
    extern __shared__ float sm[];
    float* sq = sm;                    // 64*132 — becomes sA after scores
    float* sk = sq + L_ * SQS;
    float* sv = sk + L_ * SQS;
    float* sA = sq;                    // alias

    const int bh = blockIdx.x;
    const int b  = bh >> 4;
    const int h  = bh & 15;
    const float* qb = Q + (size_t)bh * (L_ * E_);
    const float* kb = K + (size_t)bh * (L_ * E_);
    const float* vb = V + (size_t)bh * (L_ * E_);

    const int t = threadIdx.x;

    for (int idx = t; idx < (L_ * E_) / 4; idx += 256) {
        int row = idx >> 5;
        int c4  = (idx & 31) << 2;
        float4 q4 = __ldg((const float4*)(qb + row * E_ + c4));
        float4 k4 = __ldg((const float4*)(kb + row * E_ + c4));
        float4 v4 = __ldg((const float4*)(vb + row * E_ + c4));
        *(float4*)(sq + row * SQS + c4) = q4;
        *(float4*)(sk + row * SQS + c4) = k4;
        *(float4*)(sv + row * SQS + c4) = v4;
    }
    __syncthreads();

    const int l = t >> 2;
    const int c = t & 3;
    float sc[16];
#pragma unroll
    for (int j = 0; j < 16; j++) sc[j] = 0.f;

    for (int e = 0; e < E_; e += 4) {
        const float4 qv = *(const float4*)(sq + l * SQS + e);
#pragma unroll
        for (int j = 0; j < 16; j++) {
            const float4 kv = *(const float4*)(sk + (c + 4 * j) * SQS + e);
            sc[j] += qv.x * kv.x + qv.y * kv.y + qv.z * kv.z + qv.w * kv.w;
        }
    }

    // Register softmax: threads (l,0..3) are adjacent lanes -> 4-lane shfl reduce
    float mx = sc[0];
#pragma unroll
    for (int j = 1; j < 16; j++) mx = fmaxf(mx, sc[j]);
    mx = fmaxf(mx, __shfl_xor_sync(0xffffffffu, mx, 1));
    mx = fmaxf(mx, __shfl_xor_sync(0xffffffffu, mx, 2));

    float sum = 0.f;
#pragma unroll
    for (int j = 0; j < 16; j++) {
        sc[j] = __expf(0.1f * (sc[j] - mx));
        sum += sc[j];
    }
    sum += __shfl_xor_sync(0xffffffffu, sum, 1);
    sum += __shfl_xor_sync(0xffffffffu, sum, 2);
    const float inv = 1.0f / sum;

    __syncthreads();   // all sq reads done before aliasing as sA
#pragma unroll
    for (int j = 0; j < 16; j++) sA[l * SAS + c + 4 * j] = sc[j];   // unnormalized
    __syncthreads();

    float acc[32];
#pragma unroll
    for (int i = 0; i < 32; i++) acc[i] = 0.f;

    for (int s = 0; s < 64; s++) {
        const float a = sA[l * SAS + s];
#pragma unroll
        for (int j = 0; j < 8; j++) {
            const float4 vv = *(const float4*)(sv + s * SQS + (c << 2) + (j << 4));
            acc[4 * j + 0] += a * vv.x;
            acc[4 * j + 1] += a * vv.y;
            acc[4 * j + 2] += a * vv.z;
            acc[4 * j + 3] += a * vv.w;
        }
    }

    // Write fp16 A row: row = b*64+l, cols h*128 + d  (normalize here)
    const size_t base = (size_t)(b * L_ + l) * C_ + h * E_;
#pragma unroll
    for (int j = 0; j < 8; j++) {
        const int off = (c << 2) + (j << 4);
        *(uint2*)(g_a16 + base + off) =
            make_uint2(pack_h2(acc[4 * j + 0] * inv, acc[4 * j + 1] * inv),
                       pack_h2(acc[4 * j + 2] * inv, acc[4 * j + 3] * inv));
    }
}

// ---------------------------------------------------------------------------
// fp16 HMMA GEMM: out[8192,2048] = A @ W^T + bias
// Tile 128x128, 8 warps (32x64 each), BK=32, 4-stage cp.async pipeline,
// 2 CTAs/SM. smem rows padded to 80B -> conflict-free ldmatrix.
// ---------------------------------------------------------------------------
#define GBM 128
#define GBN 128
#define GBK 32
#define NKT (C_ / GBK)            // 64 k-steps
#define TROW 80                   // bytes per smem tile row
#define TILE_B (128 * TROW)       // 10240
#define STG (2 * TILE_B)          // 20480 per stage (A + B)
#define GEMM_SMEM (4 * STG)       // 81920

__device__ __forceinline__ void load_stage(uint32_t st, int m0, int n0, int k0, int t)
{
    const char* a = (const char*)(g_a16 + (size_t)m0 * C_ + k0);
    const char* bsrc = (const char*)(g_w16 + (size_t)n0 * C_ + k0);
#pragma unroll
    for (int j = 0; j < 4; j++) {
        const int idx  = t + j * 256;        // 0..1023 (16B units)
        const int tile = idx >> 9;           // 0=A, 1=B
        const int r    = (idx >> 2) & 127;
        const int cc   = idx & 3;
        const char* base = tile ? bsrc : a;
        cpa16(st + tile * TILE_B + r * TROW + cc * 16,
              base + (size_t)r * (C_ * 2) + cc * 16);
    }
}

__global__ __launch_bounds__(256, 2)
void gemm_hmma(const float* __restrict__ bias, float* __restrict__ out)
{
    extern __shared__ char smem_raw[];
    const uint32_t sb = smem_u32(smem_raw);

    const int t    = threadIdx.x;
    const int wid  = t >> 5;
    const int lane = t & 31;
    const int n0   = blockIdx.x * GBN;
    const int m0   = blockIdx.y * GBM;
    const int wm   = (wid & 3) * 32;      // 4 warps on M
    const int wn   = (wid >> 2) * 64;     // 2 warps on N

    const uint32_t a_off = (uint32_t)((lane & 15) * TROW + (lane >> 4) * 16);
    const uint32_t b_off = (uint32_t)(((lane & 7) + ((lane >> 4) << 3)) * TROW
                                      + ((lane >> 3) & 1) * 16);

    float acc[2][8][4];
#pragma unroll
    for (int i = 0; i < 2; i++)
#pragma unroll
        for (int j = 0; j < 8; j++)
#pragma unroll
            for (int q = 0; q < 4; q++) acc[i][j][q] = 0.f;

    // Prologue: stages 0..2
#pragma unroll
    for (int s = 0; s < 3; s++) {
        load_stage(sb + s * STG, m0, n0, s * GBK, t);
        cpa_commit();
    }

    for (int kt = 0; kt < NKT; kt++) {
        if (kt + 3 < NKT) {
            load_stage(sb + ((kt + 3) & 3) * STG, m0, n0, (kt + 3) * GBK, t);
            cpa_commit();
        }
        const int rem = NKT - 1 - kt;
        if (rem >= 3)      cpa_wait3();
        else if (rem == 2) cpa_wait2();
        else if (rem == 1) cpa_wait1();
        else               cpa_wait0();
        __syncthreads();

        const uint32_t st = sb + (kt & 3) * STG;
#pragma unroll
        for (int kk = 0; kk < 2; kk++) {
            const uint32_t kb = kk * 32;
            uint32_t A[2][4], Bf[4][4];
#pragma unroll
            for (int mi = 0; mi < 2; mi++)
                ldsm4(A[mi], st + a_off + (wm + mi * 16) * TROW + kb);
#pragma unroll
            for (int p = 0; p < 4; p++)
                ldsm4(Bf[p], st + TILE_B + b_off + (wn + p * 16) * TROW + kb);
#pragma unroll
            for (int mi = 0; mi < 2; mi++)
#pragma unroll
                for (int p = 0; p < 4; p++) {
                    mma_f16(acc[mi][2 * p],     A[mi], Bf[p]);
                    mma_f16(acc[mi][2 * p + 1], A[mi], Bf[p] + 2);
                }
        }
        __syncthreads();
    }

    // Epilogue: bias + store
    const int g  = lane >> 2;
    const int q2 = (lane & 3) * 2;
    float2 bvs[8];
#pragma unroll
    for (int j = 0; j < 8; j++) {
        const int col = n0 + wn + j * 8 + q2;
        bvs[j] = make_float2(__ldg(bias + col), __ldg(bias + col + 1));
    }
#pragma unroll
    for (int mi = 0; mi < 2; mi++) {
        const int row = m0 + wm + mi * 16 + g;
#pragma unroll
        for (int j = 0; j < 8; j++) {
            const int col = n0 + wn + j * 8 + q2;
            *(float2*)(out + (size_t)row * C_ + col) =
                make_float2(acc[mi][j][0] + bvs[j].x, acc[mi][j][1] + bvs[j].y);
            *(float2*)(out + (size_t)(row + 8) * C_ + col) =
                make_float2(acc[mi][j][2] + bvs[j].x, acc[mi][j][3] + bvs[j].y);
        }
    }
}

// ---------------------------------------------------------------------------
extern "C" void kernel_launch(void* const* d_in, const int* in_sizes, int n_in,
                              void* d_out, int out_size)
{
    const float* Q    = (const float*)d_in[0];
    const float* K    = (const float*)d_in[1];
    const float* V    = (const float*)d_in[2];
    const float* W    = (const float*)d_in[3];
    const float* bias = (const float*)d_in[4];
    float* out = (float*)d_out;

    cudaFuncSetAttribute(attn_kernel, cudaFuncAttributeMaxDynamicSharedMemorySize, ATTN_SMEM);
    cudaFuncSetAttribute(gemm_hmma, cudaFuncAttributeMaxDynamicSharedMemorySize, GEMM_SMEM);

    conv_w_kernel<<<(C_ * C_ / 4) / 256, 256>>>(W);
    attn_kernel<<<B_ * H_, 256, ATTN_SMEM>>>(Q, K, V);
    gemm_hmma<<<dim3(C_ / GBN, M_ / GBM), 256, GEMM_SMEM>>>(bias, out);
}

// round 5
// speedup vs baseline: 7.0113x; 1.7827x over previous
#include <cuda_runtime.h>
#include <cuda_fp16.h>
#include <cstdint>

// Problem constants
#define B_  128
#define H_  16
#define L_  64
#define E_  128
#define C_  2048          // H*E
#define M_  8192          // B*L

// fp16 operand planes (static device scratch — no allocs allowed)
__device__ __align__(16) __half g_a16[(size_t)M_ * C_];
__device__ __align__(16) __half g_w16[(size_t)C_ * C_];

// ---------------------------------------------------------------------------
// Helpers
// ---------------------------------------------------------------------------
__device__ __forceinline__ uint32_t smem_u32(const void* p) {
    uint32_t a;
    asm("{ .reg .u64 t; cvta.to.shared.u64 t, %1; cvt.u32.u64 %0, t; }" : "=r"(a) : "l"(p));
    return a;
}
__device__ __forceinline__ void cpa16(uint32_t dst, const void* src) {
    asm volatile("cp.async.cg.shared.global [%0], [%1], 16;" :: "r"(dst), "l"(src) : "memory");
}
__device__ __forceinline__ void cpa_commit() { asm volatile("cp.async.commit_group;" ::: "memory"); }
__device__ __forceinline__ void cpa_wait3()  { asm volatile("cp.async.wait_group 3;" ::: "memory"); }
__device__ __forceinline__ void cpa_wait2()  { asm volatile("cp.async.wait_group 2;" ::: "memory"); }
__device__ __forceinline__ void cpa_wait1()  { asm volatile("cp.async.wait_group 1;" ::: "memory"); }
__device__ __forceinline__ void cpa_wait0()  { asm volatile("cp.async.wait_group 0;" ::: "memory"); }

__device__ __forceinline__ void ldsm4(uint32_t* r, uint32_t addr) {
    asm volatile("ldmatrix.sync.aligned.m8n8.x4.shared.b16 {%0,%1,%2,%3}, [%4];"
                 : "=r"(r[0]), "=r"(r[1]), "=r"(r[2]), "=r"(r[3]) : "r"(addr));
}
__device__ __forceinline__ void ldsm4t(uint32_t* r, uint32_t addr) {
    asm volatile("ldmatrix.sync.aligned.m8n8.x4.trans.shared.b16 {%0,%1,%2,%3}, [%4];"
                 : "=r"(r[0]), "=r"(r[1]), "=r"(r[2]), "=r"(r[3]) : "r"(addr));
}
__device__ __forceinline__ void mma_f16(float* d, const uint32_t* a, const uint32_t* b) {
    asm volatile(
        "mma.sync.aligned.m16n8k16.row.col.f32.f16.f16.f32 "
        "{%0,%1,%2,%3}, {%4,%5,%6,%7}, {%8,%9}, {%0,%1,%2,%3};"
        : "+f"(d[0]), "+f"(d[1]), "+f"(d[2]), "+f"(d[3])
        : "r"(a[0]), "r"(a[1]), "r"(a[2]), "r"(a[3]), "r"(b[0]), "r"(b[1]));
}
__device__ __forceinline__ uint32_t pack_h2(float a, float b) {
    __half2 t = __floats2half2_rn(a, b);
    return *reinterpret_cast<uint32_t*>(&t);
}

// ---------------------------------------------------------------------------
// W conversion: fp32 -> fp16
// ---------------------------------------------------------------------------
__global__ __launch_bounds__(256)
void conv_w_kernel(const float* __restrict__ W)
{
    size_t i = (size_t)blockIdx.x * 256 + threadIdx.x;
    float4 w = __ldg(((const float4*)W) + i);
    ((uint2*)g_w16)[i] = make_uint2(pack_h2(w.x, w.y), pack_h2(w.z, w.w));
}

// ---------------------------------------------------------------------------
// Tensor-core attention: one CTA per (b,h), 4 warps x 16 rows.
// Q/K/V fp16 in smem (272B row stride -> conflict-free ldmatrix).
// S stays in registers: fragment softmax + direct P repack for P@V.
// ---------------------------------------------------------------------------
#define AS 136                               // halves per smem row (272 B)
#define ATTN_SMEM (3 * 64 * AS * 2)          // 52224 B

__global__ __launch_bounds__(128, 2)
void attn_kernel(const float* __restrict__ Q, const float* __restrict__ K,
                 const float* __restrict__ V)
{
    extern __shared__ __half smh[];
    __half* sq = smh;                 // 64 x AS
    __half* sk = sq + 64 * AS;
    __half* sv = sk + 64 * AS;

    const int bh = blockIdx.x;
    const int b  = bh >> 4;
    const int h  = bh & 15;
    const float* qb = Q + (size_t)bh * (L_ * E_);
    const float* kb = K + (size_t)bh * (L_ * E_);
    const float* vb = V + (size_t)bh * (L_ * E_);

    const int t    = threadIdx.x;
    const int wid  = t >> 5;
    const int lane = t & 31;

    // Load + fp32->fp16 convert: each warp-iter covers one 128-float row
    for (int j = 0; j < 16; j++) {
        const int idx = t + j * 128;
        const int row = idx >> 5;
        const int c4  = (idx & 31) << 2;
        float4 q4 = __ldg((const float4*)(qb + row * E_ + c4));
        float4 k4 = __ldg((const float4*)(kb + row * E_ + c4));
        float4 v4 = __ldg((const float4*)(vb + row * E_ + c4));
        *(uint2*)(sq + row * AS + c4) = make_uint2(pack_h2(q4.x, q4.y), pack_h2(q4.z, q4.w));
        *(uint2*)(sk + row * AS + c4) = make_uint2(pack_h2(k4.x, k4.y), pack_h2(k4.z, k4.w));
        *(uint2*)(sv + row * AS + c4) = make_uint2(pack_h2(v4.x, v4.y), pack_h2(v4.z, v4.w));
    }
    __syncthreads();

    const uint32_t sqb = smem_u32(sq), skb = smem_u32(sk), svb = smem_u32(sv);
    const int l0 = wid * 16;
    const int g  = lane >> 2;

    // ldmatrix per-lane base addresses
    // A (Q, non-trans x4): lanes 0-7: rows l0+0..7 @e0 | 8-15: l0+8..15 @e0 |
    //                      16-23: l0+0..7 @e0+8 | 24-31: l0+8..15 @e0+8
    const uint32_t a_base = sqb + (uint32_t)(l0 + (lane & 15)) * (AS * 2)
                          + ((lane & 16) ? 16 : 0);
    // B (K, non-trans x4): m0: s0+0..7 @e0 | m1: s0+0..7 @e0+8 | m2: s0+8..15 @e0 | m3: +8 @e0+8
    const uint32_t k_base = skb + (uint32_t)((lane & 7) + ((lane & 16) ? 8 : 0)) * (AS * 2)
                          + ((lane & 8) ? 16 : 0);
    // V (trans x4): m0: s0+0..7 @d0 | m1: s0+8..15 @d0 | m2: s0+0..7 @d0+8 | m3: +8 @d0+8
    const uint32_t v_base = svb + (uint32_t)(lane & 15) * (AS * 2)
                          + ((lane & 16) ? 16 : 0);

    // ---- S = Q @ K^T : 8 n-tiles of 8 cols, fp32 fragments -----------------
    float sc[8][4];
#pragma unroll
    for (int i = 0; i < 8; i++)
#pragma unroll
        for (int q = 0; q < 4; q++) sc[i][q] = 0.f;

#pragma unroll
    for (int e = 0; e < 8; e++) {                 // k16 steps over E=128
        uint32_t A[4];
        ldsm4(A, a_base + e * 32);
#pragma unroll
        for (int sb = 0; sb < 4; sb++) {          // s-blocks of 16
            uint32_t Bk[4];
            ldsm4(Bk, k_base + (uint32_t)(sb * 16) * (AS * 2) + e * 32);
            mma_f16(sc[2 * sb],     A, Bk);
            mma_f16(sc[2 * sb + 1], A, Bk + 2);
        }
    }

    // ---- fragment softmax (rows g and g+8 of this warp's 16) ---------------
    float mx0 = -1e30f, mx1 = -1e30f;
#pragma unroll
    for (int i = 0; i < 8; i++) {
        mx0 = fmaxf(mx0, fmaxf(sc[i][0], sc[i][1]));
        mx1 = fmaxf(mx1, fmaxf(sc[i][2], sc[i][3]));
    }
    mx0 = fmaxf(mx0, __shfl_xor_sync(0xffffffffu, mx0, 1));
    mx0 = fmaxf(mx0, __shfl_xor_sync(0xffffffffu, mx0, 2));
    mx1 = fmaxf(mx1, __shfl_xor_sync(0xffffffffu, mx1, 1));
    mx1 = fmaxf(mx1, __shfl_xor_sync(0xffffffffu, mx1, 2));

    float sum0 = 0.f, sum1 = 0.f;
#pragma unroll
    for (int i = 0; i < 8; i++) {
        sc[i][0] = __expf(0.1f * (sc[i][0] - mx0));
        sc[i][1] = __expf(0.1f * (sc[i][1] - mx0));
        sc[i][2] = __expf(0.1f * (sc[i][2] - mx1));
        sc[i][3] = __expf(0.1f * (sc[i][3] - mx1));
        sum0 += sc[i][0] + sc[i][1];
        sum1 += sc[i][2] + sc[i][3];
    }
    sum0 += __shfl_xor_sync(0xffffffffu, sum0, 1);
    sum0 += __shfl_xor_sync(0xffffffffu, sum0, 2);
    sum1 += __shfl_xor_sync(0xffffffffu, sum1, 1);
    sum1 += __shfl_xor_sync(0xffffffffu, sum1, 2);
    const float inv0 = 1.0f / sum0;
    const float inv1 = 1.0f / sum1;

    // ---- O = P @ V : P fragments repacked from sc, V via ldmatrix.trans ----
    float ac[16][4];
#pragma unroll
    for (int i = 0; i < 16; i++)
#pragma unroll
        for (int q = 0; q < 4; q++) ac[i][q] = 0.f;

#pragma unroll
    for (int j = 0; j < 4; j++) {                 // k16 steps over s=64
        uint32_t Af[4];
        Af[0] = pack_h2(sc[2 * j][0],     sc[2 * j][1]);
        Af[1] = pack_h2(sc[2 * j][2],     sc[2 * j][3]);
        Af[2] = pack_h2(sc[2 * j + 1][0], sc[2 * j + 1][1]);
        Af[3] = pack_h2(sc[2 * j + 1][2], sc[2 * j + 1][3]);
#pragma unroll
        for (int dd = 0; dd < 8; dd++) {          // d-blocks of 16
            uint32_t Bv[4];
            ldsm4t(Bv, v_base + (uint32_t)(16 * j) * (AS * 2) + dd * 32);
            mma_f16(ac[2 * dd],     Af, Bv);
            mma_f16(ac[2 * dd + 1], Af, Bv + 2);
        }
    }

    // ---- normalize + fp16 store into g_a16[(b*64+l), h*128+d] --------------
    const int q2 = (lane & 3) * 2;
    __half* out0 = g_a16 + (size_t)(b * L_ + l0 + g) * C_ + h * E_;
    __half* out1 = out0 + 8 * C_;
#pragma unroll
    for (int tt = 0; tt < 16; tt++) {
        const int col = 8 * tt + q2;
        *(uint32_t*)(out0 + col) = pack_h2(ac[tt][0] * inv0, ac[tt][1] * inv0);
        *(uint32_t*)(out1 + col) = pack_h2(ac[tt][2] * inv1, ac[tt][3] * inv1);
    }
}

// ---------------------------------------------------------------------------
// fp16 HMMA GEMM: out[8192,2048] = A @ W^T + bias  (unchanged from R4)
// ---------------------------------------------------------------------------
#define GBM 128
#define GBN 128
#define GBK 32
#define NKT (C_ / GBK)
#define TROW 80
#define TILE_B (128 * TROW)
#define STG (2 * TILE_B)
#define GEMM_SMEM (4 * STG)

__device__ __forceinline__ void load_stage(uint32_t st, int m0, int n0, int k0, int t)
{
    const char* a    = (const char*)(g_a16 + (size_t)m0 * C_ + k0);
    const char* bsrc = (const char*)(g_w16 + (size_t)n0 * C_ + k0);
#pragma unroll
    for (int j = 0; j < 4; j++) {
        const int idx  = t + j * 256;
        const int tile = idx >> 9;
        const int r    = (idx >> 2) & 127;
        const int cc   = idx & 3;
        const char* base = tile ? bsrc : a;
        cpa16(st + tile * TILE_B + r * TROW + cc * 16,
              base + (size_t)r * (C_ * 2) + cc * 16);
    }
}

__global__ __launch_bounds__(256, 2)
void gemm_hmma(const float* __restrict__ bias, float* __restrict__ out)
{
    extern __shared__ char smem_raw[];
    const uint32_t sb = smem_u32(smem_raw);

    const int t    = threadIdx.x;
    const int wid  = t >> 5;
    const int lane = t & 31;
    const int n0   = blockIdx.x * GBN;
    const int m0   = blockIdx.y * GBM;
    const int wm   = (wid & 3) * 32;
    const int wn   = (wid >> 2) * 64;

    const uint32_t a_off = (uint32_t)((lane & 15) * TROW + (lane >> 4) * 16);
    const uint32_t b_off = (uint32_t)(((lane & 7) + ((lane >> 4) << 3)) * TROW
                                      + ((lane >> 3) & 1) * 16);

    float acc[2][8][4];
#pragma unroll
    for (int i = 0; i < 2; i++)
#pragma unroll
        for (int j = 0; j < 8; j++)
#pragma unroll
            for (int q = 0; q < 4; q++) acc[i][j][q] = 0.f;

#pragma unroll
    for (int s = 0; s < 3; s++) {
        load_stage(sb + s * STG, m0, n0, s * GBK, t);
        cpa_commit();
    }

    for (int kt = 0; kt < NKT; kt++) {
        if (kt + 3 < NKT) {
            load_stage(sb + ((kt + 3) & 3) * STG, m0, n0, (kt + 3) * GBK, t);
            cpa_commit();
        }
        const int rem = NKT - 1 - kt;
        if (rem >= 3)      cpa_wait3();
        else if (rem == 2) cpa_wait2();
        else if (rem == 1) cpa_wait1();
        else               cpa_wait0();
        __syncthreads();

        const uint32_t st = sb + (kt & 3) * STG;
#pragma unroll
        for (int kk = 0; kk < 2; kk++) {
            const uint32_t kb = kk * 32;
            uint32_t A[2][4], Bf[4][4];
#pragma unroll
            for (int mi = 0; mi < 2; mi++)
                ldsm4(A[mi], st + a_off + (wm + mi * 16) * TROW + kb);
#pragma unroll
            for (int p = 0; p < 4; p++)
                ldsm4(Bf[p], st + TILE_B + b_off + (wn + p * 16) * TROW + kb);
#pragma unroll
            for (int mi = 0; mi < 2; mi++)
#pragma unroll
                for (int p = 0; p < 4; p++) {
                    mma_f16(acc[mi][2 * p],     A[mi], Bf[p]);
                    mma_f16(acc[mi][2 * p + 1], A[mi], Bf[p] + 2);
                }
        }
        __syncthreads();
    }

    const int g  = lane >> 2;
    const int q2 = (lane & 3) * 2;
    float2 bvs[8];
#pragma unroll
    for (int j = 0; j < 8; j++) {
        const int col = n0 + wn + j * 8 + q2;
        bvs[j] = make_float2(__ldg(bias + col), __ldg(bias + col + 1));
    }
#pragma unroll
    for (int mi = 0; mi < 2; mi++) {
        const int row = m0 + wm + mi * 16 + g;
#pragma unroll
        for (int j = 0; j < 8; j++) {
            const int col = n0 + wn + j * 8 + q2;
            *(float2*)(out + (size_t)row * C_ + col) =
                make_float2(acc[mi][j][0] + bvs[j].x, acc[mi][j][1] + bvs[j].y);
            *(float2*)(out + (size_t)(row + 8) * C_ + col) =
                make_float2(acc[mi][j][2] + bvs[j].x, acc[mi][j][3] + bvs[j].y);
        }
    }
}

// ---------------------------------------------------------------------------
extern "C" void kernel_launch(void* const* d_in, const int* in_sizes, int n_in,
                              void* d_out, int out_size)
{
    const float* Q    = (const float*)d_in[0];
    const float* K    = (const float*)d_in[1];
    const float* V    = (const float*)d_in[2];
    const float* W    = (const float*)d_in[3];
    const float* bias = (const float*)d_in[4];
    float* out = (float*)d_out;

    cudaFuncSetAttribute(attn_kernel, cudaFuncAttributeMaxDynamicSharedMemorySize, ATTN_SMEM);
    cudaFuncSetAttribute(gemm_hmma, cudaFuncAttributeMaxDynamicSharedMemorySize, GEMM_SMEM);

    conv_w_kernel<<<(C_ * C_ / 4) / 256, 256>>>(W);
    attn_kernel<<<B_ * H_, 128, ATTN_SMEM>>>(Q, K, V);
    gemm_hmma<<<dim3(C_ / GBN, M_ / GBM), 256, GEMM_SMEM>>>(bias, out);
}